// round 9
// baseline (speedup 1.0000x reference)
#include <cuda_runtime.h>
#include <cuda_fp16.h>
#include <cuda_bf16.h>
#include <cstdint>

#define N_NODES 50000
#define N_EDGES 1600000
#define D 64
#define CAP 128   // fixed bucket capacity per node (mean deg 32, sigma 5.66 -> 12+ sigma)

// ==================== scratch (device globals) ====================
__device__ int      g_cnt[N_NODES];
__device__ uint32_t g_csr[(size_t)N_NODES * CAP];        // {w_fp16 : dst_u16} packed
__device__ __align__(16) __half g_x16[N_NODES * D];
__device__ __align__(16) __half g_h16[N_NODES * D];
__device__ __align__(16) __half g_agg16[N_NODES * D];    // agg/cnt, fp16
__device__ __align__(16) uint2  g_Bfrag[2 * 8 * 8 * 32]; // mma-layout B fragments

// ==================== fused: CSR fill + x16 mirror + B fragments ====================
#define FILL_BLOCKS ((N_EDGES / 4 + 255) / 256)          // 1563
#define XBLOCKS     ((N_NODES * D / 4 + 255) / 256)      // 3125
#define WBLOCKS     16                                   // 2*8*8*32 / 256

__device__ __forceinline__ uint32_t pack_edge(int d, float w) {
    unsigned short h = __half_as_ushort(__float2half_rn(w));
    return (uint32_t)d | ((uint32_t)h << 16);
}

__global__ void __launch_bounds__(256) k_fill_prep(
        const int* __restrict__ src, const int* __restrict__ dst,
        const float* __restrict__ ew, const float* __restrict__ x,
        const float* __restrict__ W1, const float* __restrict__ W2) {
    int b = blockIdx.x;
    if (b < FILL_BLOCKS) {
        // ---- one-pass CSR fill into fixed-capacity buckets ----
        int e4 = b * 256 + threadIdx.x;
        if (e4 < N_EDGES / 4) {
            int4   s = __ldg((const int4*)src + e4);
            int4   d = __ldg((const int4*)dst + e4);
            float4 w = __ldg((const float4*)ew + e4);
            int p;
            p = atomicAdd(&g_cnt[s.x], 1); g_csr[(size_t)s.x * CAP + p] = pack_edge(d.x, w.x);
            p = atomicAdd(&g_cnt[s.y], 1); g_csr[(size_t)s.y * CAP + p] = pack_edge(d.y, w.y);
            p = atomicAdd(&g_cnt[s.z], 1); g_csr[(size_t)s.z * CAP + p] = pack_edge(d.z, w.z);
            p = atomicAdd(&g_cnt[s.w], 1); g_csr[(size_t)s.w * CAP + p] = pack_edge(d.w, w.w);
        }
    } else if (b < FILL_BLOCKS + XBLOCKS) {
        // ---- x -> fp16 mirror ----
        int i = (b - FILL_BLOCKS) * 256 + threadIdx.x;
        if (i < N_NODES * D / 4) {
            float4 v = __ldg((const float4*)x + i);
            __half2 h0 = __floats2half2_rn(v.x, v.y);
            __half2 h1 = __floats2half2_rn(v.z, v.w);
            uint2 u;
            u.x = reinterpret_cast<const unsigned&>(h0);
            u.y = reinterpret_cast<const unsigned&>(h1);
            ((uint2*)g_x16)[i] = u;
        }
    } else {
        // ---- W -> mma-layout fp16 B fragments ----
        // m16n8k16 .row.col, lane l (grp=l>>2,q=l&3): j = jt*8+grp, k0 = kt*16+q*2
        //   b0 = half2(W[j][k0], W[j][k0+1]), b1 = half2(W[j][k0+8], W[j][k0+9])
        int t = (b - FILL_BLOCKS - XBLOCKS) * 256 + threadIdx.x;  // 0..4095
        if (t < 2 * 8 * 8 * 32) {
            int l    = t >> 11;
            int rem  = t & 2047;
            int kt   = rem >> 8;
            int jt   = (rem >> 5) & 7;
            int lane = rem & 31;
            int grp = lane >> 2, q = lane & 3;
            int j  = jt * 8 + grp;
            int k0 = kt * 16 + q * 2;
            const float* W = l ? W2 : W1;
            __half2 h0 = __floats2half2_rn(W[j * 128 + k0],     W[j * 128 + k0 + 1]);
            __half2 h1 = __floats2half2_rn(W[j * 128 + k0 + 8], W[j * 128 + k0 + 9]);
            uint2 u;
            u.x = reinterpret_cast<const unsigned&>(h0);
            u.y = reinterpret_cast<const unsigned&>(h1);
            g_Bfrag[t] = u;
        }
    }
}

// ==================== pull aggregation (1 warp/node), fp16 out with /cnt fused ====
__device__ __forceinline__ float edge_w(uint32_t e) {
    return __half2float(__ushort_as_half((unsigned short)(e >> 16)));
}

__global__ void __launch_bounds__(256) k_aggregate(const __half* __restrict__ xin16) {
    int node = (blockIdx.x * blockDim.x + threadIdx.x) >> 5;
    int lane = threadIdx.x & 31;
    if (node >= N_NODES) return;

    const int n = g_cnt[node];
    const uint4* __restrict__ csr4 = (const uint4*)(g_csr + (size_t)node * CAP);

    float2 a0 = make_float2(0.f, 0.f), a1 = make_float2(0.f, 0.f);
    float2 a2 = make_float2(0.f, 0.f), a3 = make_float2(0.f, 0.f);

    int i = 0;
    for (; i + 4 <= n; i += 4) {
        uint4 e = __ldg(csr4 + (i >> 2));           // 4 edges, warp-broadcast LDG.128
        int d0 = e.x & 0xFFFF, d1 = e.y & 0xFFFF, d2 = e.z & 0xFFFF, d3 = e.w & 0xFFFF;
        __half2 h0 = __ldg((const __half2*)(xin16 + (size_t)d0 * D) + lane);
        __half2 h1 = __ldg((const __half2*)(xin16 + (size_t)d1 * D) + lane);
        __half2 h2 = __ldg((const __half2*)(xin16 + (size_t)d2 * D) + lane);
        __half2 h3 = __ldg((const __half2*)(xin16 + (size_t)d3 * D) + lane);
        float w0 = edge_w(e.x), w1 = edge_w(e.y), w2 = edge_w(e.z), w3 = edge_w(e.w);
        float2 v0 = __half22float2(h0), v1 = __half22float2(h1);
        float2 v2 = __half22float2(h2), v3 = __half22float2(h3);
        a0.x += v0.x * w0; a0.y += v0.y * w0;
        a1.x += v1.x * w1; a1.y += v1.y * w1;
        a2.x += v2.x * w2; a2.y += v2.y * w2;
        a3.x += v3.x * w3; a3.y += v3.y * w3;
    }
    const uint32_t* __restrict__ csr1 = (const uint32_t*)csr4;
    for (; i < n; i++) {
        uint32_t e = __ldg(csr1 + i);
        int d0 = e & 0xFFFF;
        __half2 h0 = __ldg((const __half2*)(xin16 + (size_t)d0 * D) + lane);
        float w0 = edge_w(e);
        float2 v0 = __half22float2(h0);
        a0.x += v0.x * w0; a0.y += v0.y * w0;
    }
    float inv = 1.0f / fmaxf((float)n, 1.0f);
    __half2 hv = __floats2half2_rn((a0.x + a1.x + a2.x + a3.x) * inv,
                                   (a0.y + a1.y + a2.y + a3.y) * inv);
    ((uint32_t*)(g_agg16 + (size_t)node * D))[lane] = reinterpret_cast<const unsigned&>(hv);
}

// ==================== HMMA GEMM: mma.sync m16n8k16, no smem ====================
// out[n][j] = relu( [x16[n] | agg16[n]] (fp16, K=128) @ W^T (fp16) + b[j] ), fp32 accum
// CTA = 256 threads = 8 warps; each warp: 16 nodes x 64 cols (8 j-tiles, 8 k-tiles)
__global__ void __launch_bounds__(256) k_gemm_mma(
        const __half* __restrict__ xin16, const __half* __restrict__ agg16,
        int wl, const float* __restrict__ bias,
        float* __restrict__ out32, __half* __restrict__ out16) {
    const int tid  = threadIdx.x;
    const int warp = tid >> 5, lane = tid & 31;
    const int grp  = lane >> 2, q = lane & 3;

    const int r0 = blockIdx.x * 128 + warp * 16 + grp;   // rows r0 and r0+8
    const int r0c = min(r0,     N_NODES - 1);
    const int r1c = min(r0 + 8, N_NODES - 1);

    const uint2* __restrict__ Bf = g_Bfrag + wl * (8 * 8 * 32);

    float c[8][4];
    #pragma unroll
    for (int jt = 0; jt < 8; jt++)
        c[jt][0] = c[jt][1] = c[jt][2] = c[jt][3] = 0.f;

    #pragma unroll
    for (int kt = 0; kt < 8; kt++) {
        const int kc = kt * 16 + q * 2;
        const __half* __restrict__ s = (kc < 64) ? xin16 : agg16;
        const int cc = kc & 63;
        uint32_t a0 = __ldg((const uint32_t*)(s + (size_t)r0c * D + cc));
        uint32_t a1 = __ldg((const uint32_t*)(s + (size_t)r1c * D + cc));
        uint32_t a2 = __ldg((const uint32_t*)(s + (size_t)r0c * D + cc + 8));
        uint32_t a3 = __ldg((const uint32_t*)(s + (size_t)r1c * D + cc + 8));
        #pragma unroll
        for (int jt = 0; jt < 8; jt++) {
            uint2 b = __ldg(Bf + ((kt * 8 + jt) * 32 + lane));
            asm volatile(
                "mma.sync.aligned.m16n8k16.row.col.f32.f16.f16.f32 "
                "{%0,%1,%2,%3}, {%4,%5,%6,%7}, {%8,%9}, {%0,%1,%2,%3};"
                : "+f"(c[jt][0]), "+f"(c[jt][1]), "+f"(c[jt][2]), "+f"(c[jt][3])
                : "r"(a0), "r"(a1), "r"(a2), "r"(a3), "r"(b.x), "r"(b.y));
        }
    }

    const bool w0 = (r0     < N_NODES);
    const bool w1 = (r0 + 8 < N_NODES);
    #pragma unroll
    for (int jt = 0; jt < 8; jt++) {
        const int j0 = jt * 8 + q * 2;
        float2 bb = __ldg((const float2*)(bias + j0));
        float v00 = fmaxf(c[jt][0] + bb.x, 0.f);
        float v01 = fmaxf(c[jt][1] + bb.y, 0.f);
        float v10 = fmaxf(c[jt][2] + bb.x, 0.f);
        float v11 = fmaxf(c[jt][3] + bb.y, 0.f);
        if (out16) {
            if (w0) {
                __half2 h = __floats2half2_rn(v00, v01);
                *(uint32_t*)(out16 + (size_t)r0 * D + j0) = reinterpret_cast<const unsigned&>(h);
            }
            if (w1) {
                __half2 h = __floats2half2_rn(v10, v11);
                *(uint32_t*)(out16 + (size_t)(r0 + 8) * D + j0) = reinterpret_cast<const unsigned&>(h);
            }
        } else {
            if (w0) *(float2*)(out32 + (size_t)r0 * D + j0)       = make_float2(v00, v01);
            if (w1) *(float2*)(out32 + (size_t)(r0 + 8) * D + j0) = make_float2(v10, v11);
        }
    }
}

// ==================== launch ====================
extern "C" void kernel_launch(void* const* d_in, const int* in_sizes, int n_in,
                              void* d_out, int out_size) {
    const float* x  = (const float*)d_in[0];
    const int*   ei = (const int*)  d_in[1];
    const float* ew = (const float*)d_in[2];
    const float* W1 = (const float*)d_in[3];
    const float* b1 = (const float*)d_in[4];
    const float* W2 = (const float*)d_in[5];
    const float* b2 = (const float*)d_in[6];
    float* out = (float*)d_out;

    const int* src = ei;
    const int* dst = ei + N_EDGES;

    void *p_cnt, *p_x16, *p_h16, *p_agg16;
    cudaGetSymbolAddress(&p_cnt,   g_cnt);
    cudaGetSymbolAddress(&p_x16,   g_x16);
    cudaGetSymbolAddress(&p_h16,   g_h16);
    cudaGetSymbolAddress(&p_agg16, g_agg16);
    __half* x16   = (__half*)p_x16;
    __half* h16   = (__half*)p_h16;
    __half* agg16 = (__half*)p_agg16;

    cudaMemsetAsync(p_cnt, 0, N_NODES * sizeof(int));

    // fused: one-pass CSR fill + x16 mirror + B fragments (fill blocks first)
    k_fill_prep<<<FILL_BLOCKS + XBLOCKS + WBLOCKS, 256>>>(src, dst, ew, x, W1, W2);

    const int gemm_grid = (N_NODES + 127) / 128;

    // layer 1
    k_aggregate<<<(N_NODES * 32 + 255) / 256, 256>>>(x16);
    k_gemm_mma <<<gemm_grid, 256>>>(x16, agg16, 0, b1, nullptr, h16);

    // layer 2
    k_aggregate<<<(N_NODES * 32 + 255) / 256, 256>>>(h16);
    k_gemm_mma <<<gemm_grid, 256>>>(h16, agg16, 1, b2, out, nullptr);
}

// round 10
// speedup vs baseline: 1.0003x; 1.0003x over previous
#include <cuda_runtime.h>
#include <cuda_fp16.h>
#include <cuda_bf16.h>
#include <cstdint>

#define N_NODES 50000
#define N_EDGES 1600000
#define D 64
#define CAP 128   // fixed bucket capacity per node (mean deg 32, sigma 5.66 -> 12+ sigma)

// ==================== scratch (device globals) ====================
__device__ int      g_cnt[N_NODES];
__device__ uint32_t g_csr[(size_t)N_NODES * CAP];        // {w_fp16 : dst_u16} packed
__device__ __align__(16) __half g_x16[N_NODES * D];
__device__ __align__(16) __half g_h16[N_NODES * D];
__device__ __align__(16) __half g_agg16[N_NODES * D];    // agg/cnt, fp16
__device__ __align__(16) uint2  g_Bfrag[2 * 8 * 8 * 32]; // mma-layout B fragments

// ==================== fused: CSR fill + x16 mirror + B fragments ====================
#define FILL_BLOCKS ((N_EDGES / 4 + 255) / 256)          // 1563
#define XBLOCKS     ((N_NODES * D / 4 + 255) / 256)      // 3125
#define WBLOCKS     16                                   // 2*8*8*32 / 256

__device__ __forceinline__ uint32_t pack_edge(int d, float w) {
    unsigned short h = __half_as_ushort(__float2half_rn(w));
    return (uint32_t)d | ((uint32_t)h << 16);
}

__global__ void __launch_bounds__(256) k_fill_prep(
        const int* __restrict__ src, const int* __restrict__ dst,
        const float* __restrict__ ew, const float* __restrict__ x,
        const float* __restrict__ W1, const float* __restrict__ W2) {
    int b = blockIdx.x;
    if (b < FILL_BLOCKS) {
        // ---- one-pass CSR fill into fixed-capacity buckets ----
        int e4 = b * 256 + threadIdx.x;
        if (e4 < N_EDGES / 4) {
            int4   s = __ldg((const int4*)src + e4);
            int4   d = __ldg((const int4*)dst + e4);
            float4 w = __ldg((const float4*)ew + e4);
            int p;
            p = atomicAdd(&g_cnt[s.x], 1); g_csr[(size_t)s.x * CAP + p] = pack_edge(d.x, w.x);
            p = atomicAdd(&g_cnt[s.y], 1); g_csr[(size_t)s.y * CAP + p] = pack_edge(d.y, w.y);
            p = atomicAdd(&g_cnt[s.z], 1); g_csr[(size_t)s.z * CAP + p] = pack_edge(d.z, w.z);
            p = atomicAdd(&g_cnt[s.w], 1); g_csr[(size_t)s.w * CAP + p] = pack_edge(d.w, w.w);
        }
    } else if (b < FILL_BLOCKS + XBLOCKS) {
        // ---- x -> fp16 mirror ----
        int i = (b - FILL_BLOCKS) * 256 + threadIdx.x;
        if (i < N_NODES * D / 4) {
            float4 v = __ldg((const float4*)x + i);
            __half2 h0 = __floats2half2_rn(v.x, v.y);
            __half2 h1 = __floats2half2_rn(v.z, v.w);
            uint2 u;
            u.x = reinterpret_cast<const unsigned&>(h0);
            u.y = reinterpret_cast<const unsigned&>(h1);
            ((uint2*)g_x16)[i] = u;
        }
    } else {
        // ---- W -> mma-layout fp16 B fragments ----
        // m16n8k16 .row.col, lane l (grp=l>>2,q=l&3): j = jt*8+grp, k0 = kt*16+q*2
        //   b0 = half2(W[j][k0], W[j][k0+1]), b1 = half2(W[j][k0+8], W[j][k0+9])
        int t = (b - FILL_BLOCKS - XBLOCKS) * 256 + threadIdx.x;  // 0..4095
        if (t < 2 * 8 * 8 * 32) {
            int l    = t >> 11;
            int rem  = t & 2047;
            int kt   = rem >> 8;
            int jt   = (rem >> 5) & 7;
            int lane = rem & 31;
            int grp = lane >> 2, q = lane & 3;
            int j  = jt * 8 + grp;
            int k0 = kt * 16 + q * 2;
            const float* W = l ? W2 : W1;
            __half2 h0 = __floats2half2_rn(W[j * 128 + k0],     W[j * 128 + k0 + 1]);
            __half2 h1 = __floats2half2_rn(W[j * 128 + k0 + 8], W[j * 128 + k0 + 9]);
            uint2 u;
            u.x = reinterpret_cast<const unsigned&>(h0);
            u.y = reinterpret_cast<const unsigned&>(h1);
            g_Bfrag[t] = u;
        }
    }
}

// ==================== pull aggregation (1 warp/node), fp16 out with /cnt fused ====
__device__ __forceinline__ float edge_w(uint32_t e) {
    return __half2float(__ushort_as_half((unsigned short)(e >> 16)));
}

__global__ void __launch_bounds__(256) k_aggregate(const __half* __restrict__ xin16) {
    int node = (blockIdx.x * blockDim.x + threadIdx.x) >> 5;
    int lane = threadIdx.x & 31;
    if (node >= N_NODES) return;

    const int n = g_cnt[node];
    const uint4* __restrict__ csr4 = (const uint4*)(g_csr + (size_t)node * CAP);

    float2 a0 = make_float2(0.f, 0.f), a1 = make_float2(0.f, 0.f);
    float2 a2 = make_float2(0.f, 0.f), a3 = make_float2(0.f, 0.f);

    int i = 0;
    for (; i + 4 <= n; i += 4) {
        uint4 e = __ldg(csr4 + (i >> 2));           // 4 edges, warp-broadcast LDG.128
        int d0 = e.x & 0xFFFF, d1 = e.y & 0xFFFF, d2 = e.z & 0xFFFF, d3 = e.w & 0xFFFF;
        __half2 h0 = __ldg((const __half2*)(xin16 + (size_t)d0 * D) + lane);
        __half2 h1 = __ldg((const __half2*)(xin16 + (size_t)d1 * D) + lane);
        __half2 h2 = __ldg((const __half2*)(xin16 + (size_t)d2 * D) + lane);
        __half2 h3 = __ldg((const __half2*)(xin16 + (size_t)d3 * D) + lane);
        float w0 = edge_w(e.x), w1 = edge_w(e.y), w2 = edge_w(e.z), w3 = edge_w(e.w);
        float2 v0 = __half22float2(h0), v1 = __half22float2(h1);
        float2 v2 = __half22float2(h2), v3 = __half22float2(h3);
        a0.x += v0.x * w0; a0.y += v0.y * w0;
        a1.x += v1.x * w1; a1.y += v1.y * w1;
        a2.x += v2.x * w2; a2.y += v2.y * w2;
        a3.x += v3.x * w3; a3.y += v3.y * w3;
    }
    const uint32_t* __restrict__ csr1 = (const uint32_t*)csr4;
    for (; i < n; i++) {
        uint32_t e = __ldg(csr1 + i);
        int d0 = e & 0xFFFF;
        __half2 h0 = __ldg((const __half2*)(xin16 + (size_t)d0 * D) + lane);
        float w0 = edge_w(e);
        float2 v0 = __half22float2(h0);
        a0.x += v0.x * w0; a0.y += v0.y * w0;
    }
    float inv = 1.0f / fmaxf((float)n, 1.0f);
    __half2 hv = __floats2half2_rn((a0.x + a1.x + a2.x + a3.x) * inv,
                                   (a0.y + a1.y + a2.y + a3.y) * inv);
    ((uint32_t*)(g_agg16 + (size_t)node * D))[lane] = reinterpret_cast<const unsigned&>(hv);
}

// ==================== HMMA GEMM: mma.sync m16n8k16, no smem ====================
// out[n][j] = relu( [x16[n] | agg16[n]] (fp16, K=128) @ W^T (fp16) + b[j] ), fp32 accum
// CTA = 256 threads = 8 warps; each warp: 16 nodes x 64 cols (8 j-tiles, 8 k-tiles)
__global__ void __launch_bounds__(256) k_gemm_mma(
        const __half* __restrict__ xin16, const __half* __restrict__ agg16,
        int wl, const float* __restrict__ bias,
        float* __restrict__ out32, __half* __restrict__ out16) {
    const int tid  = threadIdx.x;
    const int warp = tid >> 5, lane = tid & 31;
    const int grp  = lane >> 2, q = lane & 3;

    const int r0 = blockIdx.x * 128 + warp * 16 + grp;   // rows r0 and r0+8
    const int r0c = min(r0,     N_NODES - 1);
    const int r1c = min(r0 + 8, N_NODES - 1);

    const uint2* __restrict__ Bf = g_Bfrag + wl * (8 * 8 * 32);

    float c[8][4];
    #pragma unroll
    for (int jt = 0; jt < 8; jt++)
        c[jt][0] = c[jt][1] = c[jt][2] = c[jt][3] = 0.f;

    #pragma unroll
    for (int kt = 0; kt < 8; kt++) {
        const int kc = kt * 16 + q * 2;
        const __half* __restrict__ s = (kc < 64) ? xin16 : agg16;
        const int cc = kc & 63;
        uint32_t a0 = __ldg((const uint32_t*)(s + (size_t)r0c * D + cc));
        uint32_t a1 = __ldg((const uint32_t*)(s + (size_t)r1c * D + cc));
        uint32_t a2 = __ldg((const uint32_t*)(s + (size_t)r0c * D + cc + 8));
        uint32_t a3 = __ldg((const uint32_t*)(s + (size_t)r1c * D + cc + 8));
        #pragma unroll
        for (int jt = 0; jt < 8; jt++) {
            uint2 b = __ldg(Bf + ((kt * 8 + jt) * 32 + lane));
            asm volatile(
                "mma.sync.aligned.m16n8k16.row.col.f32.f16.f16.f32 "
                "{%0,%1,%2,%3}, {%4,%5,%6,%7}, {%8,%9}, {%0,%1,%2,%3};"
                : "+f"(c[jt][0]), "+f"(c[jt][1]), "+f"(c[jt][2]), "+f"(c[jt][3])
                : "r"(a0), "r"(a1), "r"(a2), "r"(a3), "r"(b.x), "r"(b.y));
        }
    }

    const bool w0 = (r0     < N_NODES);
    const bool w1 = (r0 + 8 < N_NODES);
    #pragma unroll
    for (int jt = 0; jt < 8; jt++) {
        const int j0 = jt * 8 + q * 2;
        float2 bb = __ldg((const float2*)(bias + j0));
        float v00 = fmaxf(c[jt][0] + bb.x, 0.f);
        float v01 = fmaxf(c[jt][1] + bb.y, 0.f);
        float v10 = fmaxf(c[jt][2] + bb.x, 0.f);
        float v11 = fmaxf(c[jt][3] + bb.y, 0.f);
        if (out16) {
            if (w0) {
                __half2 h = __floats2half2_rn(v00, v01);
                *(uint32_t*)(out16 + (size_t)r0 * D + j0) = reinterpret_cast<const unsigned&>(h);
            }
            if (w1) {
                __half2 h = __floats2half2_rn(v10, v11);
                *(uint32_t*)(out16 + (size_t)(r0 + 8) * D + j0) = reinterpret_cast<const unsigned&>(h);
            }
        } else {
            if (w0) *(float2*)(out32 + (size_t)r0 * D + j0)       = make_float2(v00, v01);
            if (w1) *(float2*)(out32 + (size_t)(r0 + 8) * D + j0) = make_float2(v10, v11);
        }
    }
}

// ==================== launch ====================
extern "C" void kernel_launch(void* const* d_in, const int* in_sizes, int n_in,
                              void* d_out, int out_size) {
    const float* x  = (const float*)d_in[0];
    const int*   ei = (const int*)  d_in[1];
    const float* ew = (const float*)d_in[2];
    const float* W1 = (const float*)d_in[3];
    const float* b1 = (const float*)d_in[4];
    const float* W2 = (const float*)d_in[5];
    const float* b2 = (const float*)d_in[6];
    float* out = (float*)d_out;

    const int* src = ei;
    const int* dst = ei + N_EDGES;

    void *p_cnt, *p_x16, *p_h16, *p_agg16;
    cudaGetSymbolAddress(&p_cnt,   g_cnt);
    cudaGetSymbolAddress(&p_x16,   g_x16);
    cudaGetSymbolAddress(&p_h16,   g_h16);
    cudaGetSymbolAddress(&p_agg16, g_agg16);
    __half* x16   = (__half*)p_x16;
    __half* h16   = (__half*)p_h16;
    __half* agg16 = (__half*)p_agg16;

    cudaMemsetAsync(p_cnt, 0, N_NODES * sizeof(int));

    // fused: one-pass CSR fill + x16 mirror + B fragments (fill blocks first)
    k_fill_prep<<<FILL_BLOCKS + XBLOCKS + WBLOCKS, 256>>>(src, dst, ew, x, W1, W2);

    const int gemm_grid = (N_NODES + 127) / 128;

    // layer 1
    k_aggregate<<<(N_NODES * 32 + 255) / 256, 256>>>(x16);
    k_gemm_mma <<<gemm_grid, 256>>>(x16, agg16, 0, b1, nullptr, h16);

    // layer 2
    k_aggregate<<<(N_NODES * 32 + 255) / 256, 256>>>(h16);
    k_gemm_mma <<<gemm_grid, 256>>>(h16, agg16, 1, b2, out, nullptr);
}